// round 9
// baseline (speedup 1.0000x reference)
#include <cuda_runtime.h>
#include <cuda_bf16.h>
#include <math.h>

#define N_NODES   3000
#define HID       64
#define MAXD      128
#define NGRP      4
#define BATCH     256
#define SEQL      50
#define MAGNA_GRID   148
#define ROWS_PER_BLK 21
#define MAGNA_THREADS (ROWS_PER_BLK * 32)
#define QKV_TILE  48

// ---------------- scratch (device globals; no allocation) ----------------
__device__ int   g_col[N_NODES * MAXD];
__device__ int   g_deg[N_NODES];     // real degree
__device__ int   g_degp[N_NODES];    // padded to multiple of 8
__device__ __align__(16) float g_q  [N_NODES * HID];
__device__ __align__(16) float g_k  [N_NODES * HID];
__device__ __align__(16) float g_v  [N_NODES * HID];
__device__ __align__(16) float g_z0 [N_NODES * HID];
__device__ __align__(16) float g_z1 [N_NODES * HID];
__device__ __align__(16) float g_z2 [N_NODES * HID];
__device__ __align__(16) float g_h  [N_NODES * HID];
__device__ float g_ss2[N_NODES];
__device__ float g_P  [NGRP * HID + 1];   // [0..255]=P[g,h], [256]=sum(Wp)
__device__ unsigned g_bar[8];             // grid-barrier counters (zeroed each replay)

// ---------------- grid barrier (148 blocks, one per SM -> deadlock-free) ----------------
__device__ __forceinline__ void grid_barrier(int slot) {
    __syncthreads();
    if (threadIdx.x == 0) {
        __threadfence();                       // release our writes
        atomicAdd(&g_bar[slot], 1u);
        unsigned v;
        do {
            asm volatile("ld.global.acquire.gpu.u32 %0, [%1];"
                         : "=r"(v) : "l"(&g_bar[slot]));
            if (v >= (unsigned)gridDim.x) break;
            __nanosleep(64);
        } while (true);
    }
    __syncthreads();
}

// ---------------- 1. build CSR from dense adj (+ zero accumulators/barriers) ----------------
__global__ void build_csr(const float* __restrict__ adj) {
    int i = blockIdx.x;
    if (i == 0) {
        for (int t = threadIdx.x; t <= NGRP * HID; t += blockDim.x) g_P[t] = 0.f;
        if (threadIdx.x < 8) g_bar[threadIdx.x] = 0u;
    }
    __shared__ int cnt;
    if (threadIdx.x == 0) cnt = 0;
    __syncthreads();
    const float4* row = reinterpret_cast<const float4*>(adj + (size_t)i * N_NODES);
    for (int j4 = threadIdx.x; j4 < N_NODES / 4; j4 += blockDim.x) {
        float4 f = row[j4];
        int j = j4 * 4;
        if (f.x > 0.f) { int p = atomicAdd(&cnt, 1); if (p < MAXD) g_col[i * MAXD + p] = j; }
        if (f.y > 0.f) { int p = atomicAdd(&cnt, 1); if (p < MAXD) g_col[i * MAXD + p] = j + 1; }
        if (f.z > 0.f) { int p = atomicAdd(&cnt, 1); if (p < MAXD) g_col[i * MAXD + p] = j + 2; }
        if (f.w > 0.f) { int p = atomicAdd(&cnt, 1); if (p < MAXD) g_col[i * MAXD + p] = j + 3; }
    }
    __syncthreads();
    int deg = min(cnt, MAXD);
    int degp = min((deg + 7) & ~7, MAXD);
    if (threadIdx.x == 0) { g_deg[i] = deg; g_degp[i] = degp; }
    for (int p = deg + (int)threadIdx.x; p < degp; p += blockDim.x) g_col[i * MAXD + p] = 0;
}

// ---------------- 2. q/k/v projections: grid (63,3), one matrix per block ----------------
// blockIdx.y = matrix, blockIdx.x = 48-row tile. 256 threads.
// thread = (col-quad qq, 3-row group rg). per c: 1 LDS.128 + 3 bcast LDS + 12 FFMA.
__global__ __launch_bounds__(256) void qkv_kernel(
    const float* __restrict__ h_ext, int hsel,
    const float* __restrict__ Wq, const float* __restrict__ Wk, const float* __restrict__ Wv)
{
    __shared__ __align__(16) float4 sW4[HID * HID / 4];   // 16 KB
    __shared__ float sh[QKV_TILE][HID + 1];               // 12.2 KB (pad 65)
    const float* hsrc = (hsel == 0) ? h_ext : g_h;
    int m = blockIdx.y;
    const float* Wm = (m == 0) ? Wq : (m == 1) ? Wk : Wv;
    int tid = threadIdx.x;
    int base = blockIdx.x * QKV_TILE;
    // stage weight matrix (float4)
    const float4* w4 = reinterpret_cast<const float4*>(Wm);
    for (int idx = tid; idx < HID * HID / 4; idx += 256) sW4[idx] = __ldg(&w4[idx]);
    // stage h tile
    for (int idx = tid; idx < QKV_TILE * HID; idx += 256) {
        int r = idx >> 6, c = idx & 63;
        int gi = base + r;
        sh[r][c] = (gi < N_NODES) ? __ldg(&hsrc[gi * HID + c]) : 0.f;
    }
    __syncthreads();

    int qq = tid & 15;             // col quad 0..15
    int rg = tid >> 4;             // row group 0..15
    int r0 = rg * 3;
    const float4* wb = &sW4[qq];   // row stride = 16 float4
    float4 a0 = make_float4(0.f, 0.f, 0.f, 0.f);
    float4 a1 = a0, a2 = a0;
#pragma unroll
    for (int c = 0; c < HID; c++) {
        float4 w = wb[c * 16];
        float h0 = sh[r0 + 0][c];
        float h1 = sh[r0 + 1][c];
        float h2 = sh[r0 + 2][c];
        a0.x += h0 * w.x; a0.y += h0 * w.y; a0.z += h0 * w.z; a0.w += h0 * w.w;
        a1.x += h1 * w.x; a1.y += h1 * w.y; a1.z += h1 * w.z; a1.w += h1 * w.w;
        a2.x += h2 * w.x; a2.y += h2 * w.y; a2.z += h2 * w.z; a2.w += h2 * w.w;
    }
    float* dst = (m == 0) ? g_q : (m == 1) ? g_k : g_v;
    float4 accs[3] = {a0, a1, a2};
#pragma unroll
    for (int i2 = 0; i2 < 3; i2++) {
        int gi = base + r0 + i2;
        if (gi < N_NODES)
            *reinterpret_cast<float4*>(&dst[gi * HID + qq * 4]) = accs[i2];
    }
}

// ---------------- 3. persistent MAGNA layer: scores+softmax+4 hops ----------------
__global__ __launch_bounds__(MAGNA_THREADS, 1) void magna_kernel(
    const float* __restrict__ resid_ext, int resid_sel, int slot_base)
{
    __shared__ __align__(16) float2 sedge[ROWS_PER_BLK][MAXD];
    int w    = threadIdx.x >> 5;
    int lane = threadIdx.x & 31;
    int half = lane >> 4;
    int hl   = lane & 15;
    int h4   = hl * 4;
    int i = blockIdx.x * ROWS_PER_BLK + w;
    bool active = (i < N_NODES);
    int deg = 0, degp = 0;
    if (active) { deg = g_deg[i]; degp = g_degp[i]; }

    // ---- phase 0: edge dots + row softmax -> smem {j*HID, coef} ----
    if (active) {
        float4 qv = *reinterpret_cast<const float4*>(&g_q[i * HID + h4]);
        const int* __restrict__ cp = &g_col[i * MAXD];
        for (int s = 0; s < degp; s += 2) {
            int e = s + half;
            int j = __ldg(&cp[e]);
            float4 kv = __ldg(reinterpret_cast<const float4*>(&g_k[j * HID + h4]));
            float d = qv.x * kv.x + qv.y * kv.y + qv.z * kv.z + qv.w * kv.w;
            d += __shfl_xor_sync(0xffffffffu, d, 8);
            d += __shfl_xor_sync(0xffffffffu, d, 4);
            d += __shfl_xor_sync(0xffffffffu, d, 2);
            d += __shfl_xor_sync(0xffffffffu, d, 1);
            if (hl == 0) sedge[w][e] = make_float2(__int_as_float(j * HID), d);
        }
        __syncwarp();
        float vals[4];
#pragma unroll
        for (int t = 0; t < 4; t++) {
            int s = lane + 32 * t;
            vals[t] = (s < deg) ? sedge[w][s].y * 0.125f : -1e30f;
        }
        float m = fmaxf(fmaxf(vals[0], vals[1]), fmaxf(vals[2], vals[3]));
#pragma unroll
        for (int o = 16; o > 0; o >>= 1) m = fmaxf(m, __shfl_xor_sync(0xffffffffu, m, o));
        float sum = 0.f;
#pragma unroll
        for (int t = 0; t < 4; t++) {
            int s = lane + 32 * t;
            float e = (s < deg) ? __expf(vals[t] - m) : 0.f;
            vals[t] = e;
            sum += e;
        }
#pragma unroll
        for (int o = 16; o > 0; o >>= 1) sum += __shfl_xor_sync(0xffffffffu, sum, o);
        float inv = 1.f / sum;
#pragma unroll
        for (int t = 0; t < 4; t++) {
            int s = lane + 32 * t;
            if (s < degp) sedge[w][s].y = (s < deg) ? vals[t] * inv : 0.f;
        }
        __syncwarp();
    }

    // ---- 4 diffusion hops ----
#pragma unroll
    for (int hop = 0; hop < 4; hop++) {
        if (hop > 0) grid_barrier(slot_base + hop - 1);
        if (active) {
            const float* __restrict__ zin =
                (hop == 0) ? g_v : (hop == 1) ? g_z0 : (hop == 2) ? g_z1 : g_z2;
            float* __restrict__ zout =
                (hop == 0) ? g_z0 : (hop == 1) ? g_z1 : (hop == 2) ? g_z2 : g_h;
            const float4* __restrict__ s4 = reinterpret_cast<const float4*>(sedge[w]);
            float ax = 0.f, ay = 0.f, az = 0.f, aw = 0.f;
            for (int s = 0; s < degp; s += 8) {
                int q = s >> 1;
#pragma unroll
                for (int t = 0; t < 4; t++) {
                    float4 e2 = s4[q + t];        // {j_even, a_even, j_odd, a_odd}
                    float cj = half ? e2.z : e2.x;
                    float cc = half ? e2.w : e2.y;
                    float4 z = __ldg(reinterpret_cast<const float4*>(&zin[__float_as_int(cj) + h4]));
                    ax += cc * z.x; ay += cc * z.y; az += cc * z.z; aw += cc * z.w;
                }
            }
            ax += __shfl_down_sync(0xffffffffu, ax, 16);
            ay += __shfl_down_sync(0xffffffffu, ay, 16);
            az += __shfl_down_sync(0xffffffffu, az, 16);
            aw += __shfl_down_sync(0xffffffffu, aw, 16);
            if (half == 0) {
                float4 v4 = __ldg(reinterpret_cast<const float4*>(&g_v[i * HID + h4]));
                float4 r;
                r.x = 0.85f * ax + 0.15f * v4.x;
                r.y = 0.85f * ay + 0.15f * v4.y;
                r.z = 0.85f * az + 0.15f * v4.z;
                r.w = 0.85f * aw + 0.15f * v4.w;
                if (hop == 3) {
                    if (resid_sel == 1) {
                        float4 e4 = __ldg(reinterpret_cast<const float4*>(&resid_ext[i * HID + h4]));
                        r.x += e4.x; r.y += e4.y; r.z += e4.z; r.w += e4.w;
                    } else {
                        float4 e4 = *reinterpret_cast<const float4*>(&g_h[i * HID + h4]);
                        r.x += e4.x; r.y += e4.y; r.z += e4.z; r.w += e4.w;
                    }
                }
                *reinterpret_cast<float4*>(&zout[i * HID + h4]) = r;
            }
        }
    }
}

// ---------------- 5. cluster softmax, ss2, P[g,h], sum(Wp) ----------------
__global__ __launch_bounds__(256) void cluster_kernel(
    const float* __restrict__ Wg, const float* __restrict__ bg, const float* __restrict__ Wp)
{
    __shared__ float sWg[HID * NGRP];
    __shared__ float sbg[NGRP];
    __shared__ float sws[256 * NGRP];
    __shared__ float sred[256];
    int tid = threadIdx.x;
    if (tid < HID * NGRP) sWg[tid] = Wg[tid];
    if (tid < NGRP) sbg[tid] = bg[tid];
    __syncthreads();
    int base = blockIdx.x * 256;
    int n = base + tid;
    float wpv = 0.f, s0 = 0.f, s1 = 0.f, s2 = 0.f, s3 = 0.f;
    if (n < N_NODES) {
        float l0 = sbg[0], l1 = sbg[1], l2 = sbg[2], l3 = sbg[3];
#pragma unroll
        for (int c = 0; c < HID; c++) {
            float hv = g_h[n * HID + c];
            l0 += hv * sWg[c * 4 + 0];
            l1 += hv * sWg[c * 4 + 1];
            l2 += hv * sWg[c * 4 + 2];
            l3 += hv * sWg[c * 4 + 3];
        }
        float m = fmaxf(fmaxf(l0, l1), fmaxf(l2, l3));
        float e0 = __expf(l0 - m), e1 = __expf(l1 - m), e2 = __expf(l2 - m), e3 = __expf(l3 - m);
        float inv = 1.f / (e0 + e1 + e2 + e3);
        s0 = e0 * inv; s1 = e1 * inv; s2 = e2 * inv; s3 = e3 * inv;
        g_ss2[n] = s0 * s0 + s1 * s1 + s2 * s2 + s3 * s3;
        wpv = Wp[n];
    }
    sws[tid * 4 + 0] = s0 * wpv;
    sws[tid * 4 + 1] = s1 * wpv;
    sws[tid * 4 + 2] = s2 * wpv;
    sws[tid * 4 + 3] = s3 * wpv;
    sred[tid] = wpv;
    __syncthreads();
    int g = tid >> 6, h = tid & 63;
    int nv = min(256, N_NODES - base);
    float acc = 0.f;
    for (int nn = 0; nn < nv; nn++)
        acc += sws[nn * 4 + g] * g_h[(base + nn) * HID + h];
    atomicAdd(&g_P[g * HID + h], acc);
    for (int s = 128; s > 0; s >>= 1) {
        __syncthreads();
        if (tid < s) sred[tid] += sred[tid + s];
    }
    __syncthreads();
    if (tid == 0) atomicAdd(&g_P[NGRP * HID], sred[0]);
}

// ---------------- 6. per-user stats + fused epilogue ----------------
__global__ __launch_bounds__(64) void finalize_kernel(
    const int* __restrict__ cate, const float* __restrict__ gamma,
    const float* __restrict__ beta, const float* __restrict__ bp, float* __restrict__ out)
{
    int b = blockIdx.x;
    int h = threadIdx.x;
    float S1 = 0.f, S2 = 0.f;
#pragma unroll 1
    for (int l = 0; l < SEQL; l++) {
        int c = cate[b * SEQL + l];
        if (c != 0) {
            float gv = g_h[c * HID + h];
            S1 += gv;
            S2 += gv * gv * g_ss2[c];
        }
    }
    const float invn = 1.f / (float)(NGRP * SEQL);
    float mean = S1 * invn;
    float var  = S2 * invn - mean * mean;
    float inv  = rsqrtf(var + 1e-5f);
    float ga = gamma[h], be = beta[h];
    float Swp = g_P[NGRP * HID];
    float bpv = bp[0];
    float k1 = inv * ga;
    float addc = be * Swp + bpv;
    float ms = mean * Swp;
#pragma unroll
    for (int g = 0; g < NGRP; g++) {
        out[(b * NGRP + g) * HID + h] = k1 * (g_P[g * HID + h] - ms) + addc;
    }
}

// ---------------- launch ----------------
extern "C" void kernel_launch(void* const* d_in, const int* in_sizes, int n_in,
                              void* d_out, int out_size)
{
    const int*   cate  = (const int*)  d_in[0];
    const float* adj   = (const float*)d_in[1];
    const float* emb   = (const float*)d_in[2];
    const float* Wq    = (const float*)d_in[3];
    const float* Wk    = (const float*)d_in[4];
    const float* Wv    = (const float*)d_in[5];
    const float* Wg    = (const float*)d_in[6];
    const float* bg    = (const float*)d_in[7];
    const float* Wp    = (const float*)d_in[8];
    const float* bp    = (const float*)d_in[9];
    const float* gamma = (const float*)d_in[10];
    const float* beta  = (const float*)d_in[11];
    float* out = (float*)d_out;

    build_csr<<<N_NODES, 128>>>(adj);

    dim3 qkv_grid((N_NODES + QKV_TILE - 1) / QKV_TILE, 3);
    for (int l = 0; l < 2; l++) {
        qkv_kernel<<<qkv_grid, 256>>>(
            emb, (l == 0) ? 0 : 1, Wq + l * HID * HID, Wk + l * HID * HID, Wv + l * HID * HID);
        magna_kernel<<<MAGNA_GRID, MAGNA_THREADS>>>(
            (l == 0) ? emb : nullptr, (l == 0) ? 1 : 2, l * 3);
    }

    cluster_kernel<<<(N_NODES + 255) / 256, 256>>>(Wg, bg, Wp);
    finalize_kernel<<<BATCH, HID>>>(cate, gamma, beta, bp, out);
}

// round 10
// speedup vs baseline: 1.0821x; 1.0821x over previous
#include <cuda_runtime.h>
#include <cuda_bf16.h>
#include <math.h>

#define N_NODES   3000
#define HID       64
#define MAXD      128
#define NGRP      4
#define BATCH     256
#define SEQL      50
#define MAGNA_GRID   148
#define ROWS_PER_BLK 21
#define MAGNA_THREADS (ROWS_PER_BLK * 32)

// dynamic smem layout for magna: [sedge 21504][sW 49152][sh 5460]
#define SM_EDGE_BYTES (ROWS_PER_BLK * MAXD * 8)
#define SM_W_BYTES    (3 * HID * HID * 4)
#define SM_H_BYTES    (ROWS_PER_BLK * (HID + 1) * 4)
#define MAGNA_SMEM    (SM_EDGE_BYTES + SM_W_BYTES + SM_H_BYTES)

// ---------------- scratch (device globals; no allocation) ----------------
__device__ int   g_col[N_NODES * MAXD];
__device__ int   g_deg[N_NODES];     // real degree
__device__ int   g_degp[N_NODES];    // padded to multiple of 8
__device__ __align__(16) float g_q  [N_NODES * HID];
__device__ __align__(16) float g_k  [N_NODES * HID];
__device__ __align__(16) float g_v  [N_NODES * HID];
__device__ __align__(16) float g_z0 [N_NODES * HID];
__device__ __align__(16) float g_z1 [N_NODES * HID];
__device__ __align__(16) float g_z2 [N_NODES * HID];
__device__ __align__(16) float g_h  [N_NODES * HID];
__device__ float g_ss2[N_NODES];
__device__ float g_P  [NGRP * HID + 1];   // [0..255]=P[g,h], [256]=sum(Wp)
__device__ unsigned g_bar[8];             // grid-barrier counters (zeroed each replay)

// ---------------- grid barrier (148 blocks, one per SM -> deadlock-free) ----------------
__device__ __forceinline__ void grid_barrier(int slot) {
    __syncthreads();
    if (threadIdx.x == 0) {
        __threadfence();                       // release our writes
        atomicAdd(&g_bar[slot], 1u);
        unsigned v;
        do {
            asm volatile("ld.global.acquire.gpu.u32 %0, [%1];"
                         : "=r"(v) : "l"(&g_bar[slot]));
            if (v >= (unsigned)gridDim.x) break;
            __nanosleep(64);
        } while (true);
    }
    __syncthreads();
}

// ---------------- 1. build CSR from dense adj (+ zero accumulators/barriers) ----------------
__global__ void build_csr(const float* __restrict__ adj) {
    int i = blockIdx.x;
    if (i == 0) {
        for (int t = threadIdx.x; t <= NGRP * HID; t += blockDim.x) g_P[t] = 0.f;
        if (threadIdx.x < 8) g_bar[threadIdx.x] = 0u;
    }
    __shared__ int cnt;
    if (threadIdx.x == 0) cnt = 0;
    __syncthreads();
    const float4* row = reinterpret_cast<const float4*>(adj + (size_t)i * N_NODES);
    for (int j4 = threadIdx.x; j4 < N_NODES / 4; j4 += blockDim.x) {
        float4 f = row[j4];
        int j = j4 * 4;
        if (f.x > 0.f) { int p = atomicAdd(&cnt, 1); if (p < MAXD) g_col[i * MAXD + p] = j; }
        if (f.y > 0.f) { int p = atomicAdd(&cnt, 1); if (p < MAXD) g_col[i * MAXD + p] = j + 1; }
        if (f.z > 0.f) { int p = atomicAdd(&cnt, 1); if (p < MAXD) g_col[i * MAXD + p] = j + 2; }
        if (f.w > 0.f) { int p = atomicAdd(&cnt, 1); if (p < MAXD) g_col[i * MAXD + p] = j + 3; }
    }
    __syncthreads();
    int deg = min(cnt, MAXD);
    int degp = min((deg + 7) & ~7, MAXD);
    if (threadIdx.x == 0) { g_deg[i] = deg; g_degp[i] = degp; }
    for (int p = deg + (int)threadIdx.x; p < degp; p += blockDim.x) g_col[i * MAXD + p] = 0;
}

// ---------------- 2. persistent MAGNA layer: QKV + scores + softmax + 4 hops ----------------
// grid = 148 (one block per SM), 21 warps/block, warp-per-row.
// Barrier slots used: slot_base+0 (after QKV), slot_base+1..3 (between hops).
__global__ __launch_bounds__(MAGNA_THREADS, 1) void magna_kernel(
    const float* __restrict__ h_ext, int hsel,
    const float* __restrict__ Wq, const float* __restrict__ Wk, const float* __restrict__ Wv,
    const float* __restrict__ resid_ext, int resid_sel, int slot_base)
{
    extern __shared__ char dyn[];
    float2 (*sedge)[MAXD] = reinterpret_cast<float2(*)[MAXD]>(dyn);
    float* sW = reinterpret_cast<float*>(dyn + SM_EDGE_BYTES);
    float* sh = reinterpret_cast<float*>(dyn + SM_EDGE_BYTES + SM_W_BYTES);

    int tid  = threadIdx.x;
    int w    = tid >> 5;
    int lane = tid & 31;
    int half = lane >> 4;
    int hl   = lane & 15;
    int h4   = hl * 4;
    int base = blockIdx.x * ROWS_PER_BLK;
    int i = base + w;
    bool active = (i < N_NODES);

    const float* hsrc = (hsel == 0) ? h_ext : g_h;

    // ---- phase A: stage weights (48 KB) + own h tile into smem ----
    {
        float4* sW4 = reinterpret_cast<float4*>(sW);
        const float4* wq4 = reinterpret_cast<const float4*>(Wq);
        const float4* wk4 = reinterpret_cast<const float4*>(Wk);
        const float4* wv4 = reinterpret_cast<const float4*>(Wv);
        for (int idx = tid; idx < HID * HID / 4; idx += MAGNA_THREADS) {
            sW4[idx]        = __ldg(&wq4[idx]);
            sW4[1024 + idx] = __ldg(&wk4[idx]);
            sW4[2048 + idx] = __ldg(&wv4[idx]);
        }
        for (int idx = tid; idx < ROWS_PER_BLK * HID; idx += MAGNA_THREADS) {
            int r = idx >> 6, c = idx & 63;
            int gi = base + r;
            sh[r * (HID + 1) + c] = (gi < N_NODES) ? __ldg(&hsrc[gi * HID + c]) : 0.f;
        }
    }
    __syncthreads();

    // ---- phase B: QKV for own 21 rows (336 threads: mat x quad x 3-row group) ----
    if (tid < 336) {
        int m  = tid / 112;
        int rm = tid % 112;
        int quad = rm & 15;
        int rg   = rm >> 4;       // 0..6
        int r0   = rg * 3;
        const float4* wb = reinterpret_cast<const float4*>(sW) + m * 1024 + quad;
        float4 a0 = make_float4(0.f, 0.f, 0.f, 0.f);
        float4 a1 = a0, a2 = a0;
#pragma unroll
        for (int c = 0; c < HID; c++) {
            float4 ww = wb[c * 16];
            float h0 = sh[(r0 + 0) * (HID + 1) + c];
            float h1 = sh[(r0 + 1) * (HID + 1) + c];
            float h2 = sh[(r0 + 2) * (HID + 1) + c];
            a0.x += h0 * ww.x; a0.y += h0 * ww.y; a0.z += h0 * ww.z; a0.w += h0 * ww.w;
            a1.x += h1 * ww.x; a1.y += h1 * ww.y; a1.z += h1 * ww.z; a1.w += h1 * ww.w;
            a2.x += h2 * ww.x; a2.y += h2 * ww.y; a2.z += h2 * ww.z; a2.w += h2 * ww.w;
        }
        float* dst = (m == 0) ? g_q : (m == 1) ? g_k : g_v;
        float4 accs[3] = {a0, a1, a2};
#pragma unroll
        for (int i2 = 0; i2 < 3; i2++) {
            int gi = base + r0 + i2;
            if (gi < N_NODES)
                *reinterpret_cast<float4*>(&dst[gi * HID + quad * 4]) = accs[i2];
        }
    }
    grid_barrier(slot_base);      // all q/k/v visible chip-wide

    int deg = 0, degp = 0;
    if (active) { deg = g_deg[i]; degp = g_degp[i]; }

    // ---- phase C: edge dots + row softmax -> smem {j*HID, coef} ----
    if (active) {
        float4 qv = *reinterpret_cast<const float4*>(&g_q[i * HID + h4]);
        const int* __restrict__ cp = &g_col[i * MAXD];
        for (int s = 0; s < degp; s += 2) {
            int e = s + half;
            int j = __ldg(&cp[e]);
            float4 kv = __ldg(reinterpret_cast<const float4*>(&g_k[j * HID + h4]));
            float d = qv.x * kv.x + qv.y * kv.y + qv.z * kv.z + qv.w * kv.w;
            d += __shfl_xor_sync(0xffffffffu, d, 8);
            d += __shfl_xor_sync(0xffffffffu, d, 4);
            d += __shfl_xor_sync(0xffffffffu, d, 2);
            d += __shfl_xor_sync(0xffffffffu, d, 1);
            if (hl == 0) sedge[w][e] = make_float2(__int_as_float(j * HID), d);
        }
        __syncwarp();
        float vals[4];
#pragma unroll
        for (int t = 0; t < 4; t++) {
            int s = lane + 32 * t;
            vals[t] = (s < deg) ? sedge[w][s].y * 0.125f : -1e30f;
        }
        float m = fmaxf(fmaxf(vals[0], vals[1]), fmaxf(vals[2], vals[3]));
#pragma unroll
        for (int o = 16; o > 0; o >>= 1) m = fmaxf(m, __shfl_xor_sync(0xffffffffu, m, o));
        float sum = 0.f;
#pragma unroll
        for (int t = 0; t < 4; t++) {
            int s = lane + 32 * t;
            float e = (s < deg) ? __expf(vals[t] - m) : 0.f;
            vals[t] = e;
            sum += e;
        }
#pragma unroll
        for (int o = 16; o > 0; o >>= 1) sum += __shfl_xor_sync(0xffffffffu, sum, o);
        float inv = 1.f / sum;
#pragma unroll
        for (int t = 0; t < 4; t++) {
            int s = lane + 32 * t;
            if (s < degp) sedge[w][s].y = (s < deg) ? vals[t] * inv : 0.f;
        }
        __syncwarp();
    }

    // ---- phase D: 4 diffusion hops ----
#pragma unroll
    for (int hop = 0; hop < 4; hop++) {
        if (hop > 0) grid_barrier(slot_base + hop);
        if (active) {
            const float* __restrict__ zin =
                (hop == 0) ? g_v : (hop == 1) ? g_z0 : (hop == 2) ? g_z1 : g_z2;
            float* __restrict__ zout =
                (hop == 0) ? g_z0 : (hop == 1) ? g_z1 : (hop == 2) ? g_z2 : g_h;
            const float4* __restrict__ s4 = reinterpret_cast<const float4*>(sedge[w]);
            float ax = 0.f, ay = 0.f, az = 0.f, aw = 0.f;
            for (int s = 0; s < degp; s += 8) {
                int q = s >> 1;
#pragma unroll
                for (int t = 0; t < 4; t++) {
                    float4 e2 = s4[q + t];        // {j_even, a_even, j_odd, a_odd}
                    float cj = half ? e2.z : e2.x;
                    float cc = half ? e2.w : e2.y;
                    float4 z = __ldg(reinterpret_cast<const float4*>(&zin[__float_as_int(cj) + h4]));
                    ax += cc * z.x; ay += cc * z.y; az += cc * z.z; aw += cc * z.w;
                }
            }
            ax += __shfl_down_sync(0xffffffffu, ax, 16);
            ay += __shfl_down_sync(0xffffffffu, ay, 16);
            az += __shfl_down_sync(0xffffffffu, az, 16);
            aw += __shfl_down_sync(0xffffffffu, aw, 16);
            if (half == 0) {
                float4 v4 = __ldg(reinterpret_cast<const float4*>(&g_v[i * HID + h4]));
                float4 r;
                r.x = 0.85f * ax + 0.15f * v4.x;
                r.y = 0.85f * ay + 0.15f * v4.y;
                r.z = 0.85f * az + 0.15f * v4.z;
                r.w = 0.85f * aw + 0.15f * v4.w;
                if (hop == 3) {
                    if (resid_sel == 1) {
                        float4 e4 = __ldg(reinterpret_cast<const float4*>(&resid_ext[i * HID + h4]));
                        r.x += e4.x; r.y += e4.y; r.z += e4.z; r.w += e4.w;
                    } else {
                        float4 e4 = *reinterpret_cast<const float4*>(&g_h[i * HID + h4]);
                        r.x += e4.x; r.y += e4.y; r.z += e4.z; r.w += e4.w;
                    }
                }
                *reinterpret_cast<float4*>(&zout[i * HID + h4]) = r;
            }
        }
    }
}

// ---------------- 3. cluster softmax, ss2, P[g,h], sum(Wp) ----------------
__global__ __launch_bounds__(256) void cluster_kernel(
    const float* __restrict__ Wg, const float* __restrict__ bg, const float* __restrict__ Wp)
{
    __shared__ float sWg[HID * NGRP];
    __shared__ float sbg[NGRP];
    __shared__ float sws[256 * NGRP];
    __shared__ float sred[256];
    int tid = threadIdx.x;
    if (tid < HID * NGRP) sWg[tid] = Wg[tid];
    if (tid < NGRP) sbg[tid] = bg[tid];
    __syncthreads();
    int base = blockIdx.x * 256;
    int n = base + tid;
    float wpv = 0.f, s0 = 0.f, s1 = 0.f, s2 = 0.f, s3 = 0.f;
    if (n < N_NODES) {
        float l0 = sbg[0], l1 = sbg[1], l2 = sbg[2], l3 = sbg[3];
#pragma unroll
        for (int c = 0; c < HID; c++) {
            float hv = g_h[n * HID + c];
            l0 += hv * sWg[c * 4 + 0];
            l1 += hv * sWg[c * 4 + 1];
            l2 += hv * sWg[c * 4 + 2];
            l3 += hv * sWg[c * 4 + 3];
        }
        float m = fmaxf(fmaxf(l0, l1), fmaxf(l2, l3));
        float e0 = __expf(l0 - m), e1 = __expf(l1 - m), e2 = __expf(l2 - m), e3 = __expf(l3 - m);
        float inv = 1.f / (e0 + e1 + e2 + e3);
        s0 = e0 * inv; s1 = e1 * inv; s2 = e2 * inv; s3 = e3 * inv;
        g_ss2[n] = s0 * s0 + s1 * s1 + s2 * s2 + s3 * s3;
        wpv = Wp[n];
    }
    sws[tid * 4 + 0] = s0 * wpv;
    sws[tid * 4 + 1] = s1 * wpv;
    sws[tid * 4 + 2] = s2 * wpv;
    sws[tid * 4 + 3] = s3 * wpv;
    sred[tid] = wpv;
    __syncthreads();
    int g = tid >> 6, h = tid & 63;
    int nv = min(256, N_NODES - base);
    float acc = 0.f;
    for (int nn = 0; nn < nv; nn++)
        acc += sws[nn * 4 + g] * g_h[(base + nn) * HID + h];
    atomicAdd(&g_P[g * HID + h], acc);
    for (int s = 128; s > 0; s >>= 1) {
        __syncthreads();
        if (tid < s) sred[tid] += sred[tid + s];
    }
    __syncthreads();
    if (tid == 0) atomicAdd(&g_P[NGRP * HID], sred[0]);
}

// ---------------- 4. per-user stats + fused epilogue ----------------
__global__ __launch_bounds__(64) void finalize_kernel(
    const int* __restrict__ cate, const float* __restrict__ gamma,
    const float* __restrict__ beta, const float* __restrict__ bp, float* __restrict__ out)
{
    int b = blockIdx.x;
    int h = threadIdx.x;
    float S1 = 0.f, S2 = 0.f;
#pragma unroll 1
    for (int l = 0; l < SEQL; l++) {
        int c = cate[b * SEQL + l];
        if (c != 0) {
            float gv = g_h[c * HID + h];
            S1 += gv;
            S2 += gv * gv * g_ss2[c];
        }
    }
    const float invn = 1.f / (float)(NGRP * SEQL);
    float mean = S1 * invn;
    float var  = S2 * invn - mean * mean;
    float inv  = rsqrtf(var + 1e-5f);
    float ga = gamma[h], be = beta[h];
    float Swp = g_P[NGRP * HID];
    float bpv = bp[0];
    float k1 = inv * ga;
    float addc = be * Swp + bpv;
    float ms = mean * Swp;
#pragma unroll
    for (int g = 0; g < NGRP; g++) {
        out[(b * NGRP + g) * HID + h] = k1 * (g_P[g * HID + h] - ms) + addc;
    }
}

// ---------------- launch ----------------
extern "C" void kernel_launch(void* const* d_in, const int* in_sizes, int n_in,
                              void* d_out, int out_size)
{
    const int*   cate  = (const int*)  d_in[0];
    const float* adj   = (const float*)d_in[1];
    const float* emb   = (const float*)d_in[2];
    const float* Wq    = (const float*)d_in[3];
    const float* Wk    = (const float*)d_in[4];
    const float* Wv    = (const float*)d_in[5];
    const float* Wg    = (const float*)d_in[6];
    const float* bg    = (const float*)d_in[7];
    const float* Wp    = (const float*)d_in[8];
    const float* bp    = (const float*)d_in[9];
    const float* gamma = (const float*)d_in[10];
    const float* beta  = (const float*)d_in[11];
    float* out = (float*)d_out;

    static bool attr_set = false;
    if (!attr_set) {
        cudaFuncSetAttribute(magna_kernel,
                             cudaFuncAttributeMaxDynamicSharedMemorySize, MAGNA_SMEM);
        attr_set = true;
    }

    build_csr<<<N_NODES, 128>>>(adj);

    for (int l = 0; l < 2; l++) {
        magna_kernel<<<MAGNA_GRID, MAGNA_THREADS, MAGNA_SMEM>>>(
            emb, (l == 0) ? 0 : 1,
            Wq + l * HID * HID, Wk + l * HID * HID, Wv + l * HID * HID,
            (l == 0) ? emb : nullptr, (l == 0) ? 1 : 2, l * 4);
    }

    cluster_kernel<<<(N_NODES + 255) / 256, 256>>>(Wg, bg, Wp);
    finalize_kernel<<<BATCH, HID>>>(cate, gamma, beta, bp, out);
}

// round 11
// speedup vs baseline: 1.0855x; 1.0032x over previous
#include <cuda_runtime.h>
#include <cuda_bf16.h>
#include <math.h>

#define N_NODES   3000
#define HID       64
#define MAXD      128
#define NGRP      4
#define BATCH     256
#define SEQL      50
#define MAGNA_GRID   148
#define ROWS_PER_BLK 21
#define MAGNA_THREADS (ROWS_PER_BLK * 32)

// dynamic smem layout for magna: [sedge 21504][sW 49152][sh 5460]
#define SM_EDGE_BYTES (ROWS_PER_BLK * MAXD * 8)
#define SM_W_BYTES    (3 * HID * HID * 4)
#define SM_H_BYTES    (ROWS_PER_BLK * (HID + 1) * 4)
#define MAGNA_SMEM    (SM_EDGE_BYTES + SM_W_BYTES + SM_H_BYTES)

// ---------------- scratch (device globals; no allocation) ----------------
__device__ int   g_col[N_NODES * MAXD];
__device__ int   g_deg[N_NODES];     // real degree
__device__ int   g_degp[N_NODES];    // padded to multiple of 8
__device__ __align__(16) float g_q  [N_NODES * HID];
__device__ __align__(16) float g_k  [N_NODES * HID];
__device__ __align__(16) float g_v  [N_NODES * HID];
__device__ __align__(16) float g_z0 [N_NODES * HID];
__device__ __align__(16) float g_z1 [N_NODES * HID];
__device__ __align__(16) float g_z2 [N_NODES * HID];
__device__ __align__(16) float g_h  [N_NODES * HID];
__device__ float g_ss2[N_NODES];
__device__ float g_P  [NGRP * HID + 1];   // [0..255]=P[g,h], [256]=sum(Wp)
__device__ unsigned g_bar[8];             // grid-barrier counters (zeroed each replay)

// ---------------- grid barrier (148 blocks, one per SM -> deadlock-free) ----------------
__device__ __forceinline__ void grid_barrier(int slot) {
    __syncthreads();
    if (threadIdx.x == 0) {
        __threadfence();                       // release our writes
        atomicAdd(&g_bar[slot], 1u);
        unsigned v;
        do {
            asm volatile("ld.global.acquire.gpu.u32 %0, [%1];"
                         : "=r"(v) : "l"(&g_bar[slot]));
            if (v >= (unsigned)gridDim.x) break;
            __nanosleep(64);
        } while (true);
    }
    __syncthreads();
}

// ---------------- 1. build CSR from dense adj (+ zero accumulators/barriers) ----------------
__global__ void build_csr(const float* __restrict__ adj) {
    int i = blockIdx.x;
    if (i == 0) {
        for (int t = threadIdx.x; t <= NGRP * HID; t += blockDim.x) g_P[t] = 0.f;
        if (threadIdx.x < 8) g_bar[threadIdx.x] = 0u;
    }
    __shared__ int cnt;
    if (threadIdx.x == 0) cnt = 0;
    __syncthreads();
    const float4* row = reinterpret_cast<const float4*>(adj + (size_t)i * N_NODES);
    for (int j4 = threadIdx.x; j4 < N_NODES / 4; j4 += blockDim.x) {
        float4 f = row[j4];
        int j = j4 * 4;
        if (f.x > 0.f) { int p = atomicAdd(&cnt, 1); if (p < MAXD) g_col[i * MAXD + p] = j; }
        if (f.y > 0.f) { int p = atomicAdd(&cnt, 1); if (p < MAXD) g_col[i * MAXD + p] = j + 1; }
        if (f.z > 0.f) { int p = atomicAdd(&cnt, 1); if (p < MAXD) g_col[i * MAXD + p] = j + 2; }
        if (f.w > 0.f) { int p = atomicAdd(&cnt, 1); if (p < MAXD) g_col[i * MAXD + p] = j + 3; }
    }
    __syncthreads();
    int deg = min(cnt, MAXD);
    int degp = min((deg + 7) & ~7, MAXD);
    if (threadIdx.x == 0) { g_deg[i] = deg; g_degp[i] = degp; }
    for (int p = deg + (int)threadIdx.x; p < degp; p += blockDim.x) g_col[i * MAXD + p] = 0;
}

// ---------------- 2. persistent MAGNA layer: QKV + scores + softmax + 4 hops ----------------
__global__ __launch_bounds__(MAGNA_THREADS, 1) void magna_kernel(
    const float* __restrict__ h_ext, int hsel,
    const float* __restrict__ Wq, const float* __restrict__ Wk, const float* __restrict__ Wv,
    const float* __restrict__ resid_ext, int resid_sel, int slot_base)
{
    extern __shared__ char dyn[];
    float2 (*sedge)[MAXD] = reinterpret_cast<float2(*)[MAXD]>(dyn);
    float* sW = reinterpret_cast<float*>(dyn + SM_EDGE_BYTES);
    float* sh = reinterpret_cast<float*>(dyn + SM_EDGE_BYTES + SM_W_BYTES);

    int tid  = threadIdx.x;
    int w    = tid >> 5;
    int lane = tid & 31;
    int half = lane >> 4;
    int hl   = lane & 15;
    int h4   = hl * 4;
    int base = blockIdx.x * ROWS_PER_BLK;
    int i = base + w;
    bool active = (i < N_NODES);

    const float* hsrc = (hsel == 0) ? h_ext : g_h;

    // ---- phase A: stage weights (48 KB) + own h tile into smem ----
    {
        float4* sW4 = reinterpret_cast<float4*>(sW);
        const float4* wq4 = reinterpret_cast<const float4*>(Wq);
        const float4* wk4 = reinterpret_cast<const float4*>(Wk);
        const float4* wv4 = reinterpret_cast<const float4*>(Wv);
        for (int idx = tid; idx < HID * HID / 4; idx += MAGNA_THREADS) {
            sW4[idx]        = __ldg(&wq4[idx]);
            sW4[1024 + idx] = __ldg(&wk4[idx]);
            sW4[2048 + idx] = __ldg(&wv4[idx]);
        }
        for (int idx = tid; idx < ROWS_PER_BLK * HID; idx += MAGNA_THREADS) {
            int r = idx >> 6, c = idx & 63;
            int gi = base + r;
            sh[r * (HID + 1) + c] = (gi < N_NODES) ? __ldg(&hsrc[gi * HID + c]) : 0.f;
        }
    }
    __syncthreads();

    // ---- phase B: QKV for own 21 rows (336 threads: mat x quad x 3-row group) ----
    if (tid < 336) {
        int m  = tid / 112;
        int rm = tid % 112;
        int quad = rm & 15;
        int rg   = rm >> 4;       // 0..6
        int r0   = rg * 3;
        const float4* wb = reinterpret_cast<const float4*>(sW) + m * 1024 + quad;
        float4 a0 = make_float4(0.f, 0.f, 0.f, 0.f);
        float4 a1 = a0, a2 = a0;
#pragma unroll
        for (int c = 0; c < HID; c++) {
            float4 ww = wb[c * 16];
            float h0 = sh[(r0 + 0) * (HID + 1) + c];
            float h1 = sh[(r0 + 1) * (HID + 1) + c];
            float h2 = sh[(r0 + 2) * (HID + 1) + c];
            a0.x += h0 * ww.x; a0.y += h0 * ww.y; a0.z += h0 * ww.z; a0.w += h0 * ww.w;
            a1.x += h1 * ww.x; a1.y += h1 * ww.y; a1.z += h1 * ww.z; a1.w += h1 * ww.w;
            a2.x += h2 * ww.x; a2.y += h2 * ww.y; a2.z += h2 * ww.z; a2.w += h2 * ww.w;
        }
        float* dst = (m == 0) ? g_q : (m == 1) ? g_k : g_v;
        float4 accs[3] = {a0, a1, a2};
#pragma unroll
        for (int i2 = 0; i2 < 3; i2++) {
            int gi = base + r0 + i2;
            if (gi < N_NODES)
                *reinterpret_cast<float4*>(&dst[gi * HID + quad * 4]) = accs[i2];
        }
    }
    grid_barrier(slot_base);      // all q/k/v visible chip-wide

    int deg = 0, degp = 0;
    if (active) { deg = g_deg[i]; degp = g_degp[i]; }

    // ---- phase C: edge dots + row softmax -> smem {j*HID, coef} ----
    if (active) {
        float4 qv = *reinterpret_cast<const float4*>(&g_q[i * HID + h4]);
        const int* __restrict__ cp = &g_col[i * MAXD];
        for (int s = 0; s < degp; s += 2) {
            int e = s + half;
            int j = __ldg(&cp[e]);
            float4 kv = __ldg(reinterpret_cast<const float4*>(&g_k[j * HID + h4]));
            float d = qv.x * kv.x + qv.y * kv.y + qv.z * kv.z + qv.w * kv.w;
            d += __shfl_xor_sync(0xffffffffu, d, 8);
            d += __shfl_xor_sync(0xffffffffu, d, 4);
            d += __shfl_xor_sync(0xffffffffu, d, 2);
            d += __shfl_xor_sync(0xffffffffu, d, 1);
            if (hl == 0) sedge[w][e] = make_float2(__int_as_float(j * HID), d);
        }
        __syncwarp();
        float vals[4];
#pragma unroll
        for (int t = 0; t < 4; t++) {
            int s = lane + 32 * t;
            vals[t] = (s < deg) ? sedge[w][s].y * 0.125f : -1e30f;
        }
        float m = fmaxf(fmaxf(vals[0], vals[1]), fmaxf(vals[2], vals[3]));
#pragma unroll
        for (int o = 16; o > 0; o >>= 1) m = fmaxf(m, __shfl_xor_sync(0xffffffffu, m, o));
        float sum = 0.f;
#pragma unroll
        for (int t = 0; t < 4; t++) {
            int s = lane + 32 * t;
            float e = (s < deg) ? __expf(vals[t] - m) : 0.f;
            vals[t] = e;
            sum += e;
        }
#pragma unroll
        for (int o = 16; o > 0; o >>= 1) sum += __shfl_xor_sync(0xffffffffu, sum, o);
        float inv = 1.f / sum;
#pragma unroll
        for (int t = 0; t < 4; t++) {
            int s = lane + 32 * t;
            if (s < degp) sedge[w][s].y = (s < deg) ? vals[t] * inv : 0.f;
        }
        __syncwarp();
    }

    // ---- phase D: 4 diffusion hops ----
#pragma unroll
    for (int hop = 0; hop < 4; hop++) {
        if (hop > 0) grid_barrier(slot_base + hop);
        if (active) {
            const float* __restrict__ zin =
                (hop == 0) ? g_v : (hop == 1) ? g_z0 : (hop == 2) ? g_z1 : g_z2;
            float* __restrict__ zout =
                (hop == 0) ? g_z0 : (hop == 1) ? g_z1 : (hop == 2) ? g_z2 : g_h;
            const float4* __restrict__ s4 = reinterpret_cast<const float4*>(sedge[w]);
            float ax = 0.f, ay = 0.f, az = 0.f, aw = 0.f;
            for (int s = 0; s < degp; s += 8) {
                int q = s >> 1;
#pragma unroll
                for (int t = 0; t < 4; t++) {
                    float4 e2 = s4[q + t];        // {j_even, a_even, j_odd, a_odd}
                    float cj = half ? e2.z : e2.x;
                    float cc = half ? e2.w : e2.y;
                    float4 z = __ldg(reinterpret_cast<const float4*>(&zin[__float_as_int(cj) + h4]));
                    ax += cc * z.x; ay += cc * z.y; az += cc * z.z; aw += cc * z.w;
                }
            }
            ax += __shfl_down_sync(0xffffffffu, ax, 16);
            ay += __shfl_down_sync(0xffffffffu, ay, 16);
            az += __shfl_down_sync(0xffffffffu, az, 16);
            aw += __shfl_down_sync(0xffffffffu, aw, 16);
            if (half == 0) {
                float4 v4 = __ldg(reinterpret_cast<const float4*>(&g_v[i * HID + h4]));
                float4 r;
                r.x = 0.85f * ax + 0.15f * v4.x;
                r.y = 0.85f * ay + 0.15f * v4.y;
                r.z = 0.85f * az + 0.15f * v4.z;
                r.w = 0.85f * aw + 0.15f * v4.w;
                if (hop == 3) {
                    if (resid_sel == 1) {
                        float4 e4 = __ldg(reinterpret_cast<const float4*>(&resid_ext[i * HID + h4]));
                        r.x += e4.x; r.y += e4.y; r.z += e4.z; r.w += e4.w;
                    } else {
                        float4 e4 = *reinterpret_cast<const float4*>(&g_h[i * HID + h4]);
                        r.x += e4.x; r.y += e4.y; r.z += e4.z; r.w += e4.w;
                    }
                }
                *reinterpret_cast<float4*>(&zout[i * HID + h4]) = r;
            }
        }
    }
}

// ---------------- 3. cluster softmax, ss2, P[g,h], sum(Wp) ----------------
// grid = 94 blocks x 32 nodes. g_h tile staged once, reused for logits + P-reduction.
__global__ __launch_bounds__(256) void cluster_kernel(
    const float* __restrict__ Wg, const float* __restrict__ bg, const float* __restrict__ Wp)
{
    __shared__ float sh_h[32][HID + 1];     // 8.3 KB
    __shared__ float sWg[HID * NGRP];
    __shared__ float sbg[NGRP];
    __shared__ float sws[32][NGRP];
    __shared__ float sswp[32];
    int tid = threadIdx.x;
    int base = blockIdx.x * 32;
    if (tid < HID * NGRP) sWg[tid] = Wg[tid];
    if (tid < NGRP) sbg[tid] = bg[tid];
    // stage 32 h rows (coalesced)
    for (int idx = tid; idx < 32 * HID; idx += 256) {
        int r = idx >> 6, c = idx & 63;
        int gi = base + r;
        sh_h[r][c] = (gi < N_NODES) ? g_h[gi * HID + c] : 0.f;
    }
    __syncthreads();

    // logits: 8 threads per node, 8 columns each
    int nn = tid >> 3, p = tid & 7;
    float l0 = 0.f, l1 = 0.f, l2 = 0.f, l3 = 0.f;
#pragma unroll
    for (int cc = 0; cc < 8; cc++) {
        int c = p * 8 + cc;
        float hv = sh_h[nn][c];
        l0 += hv * sWg[c * 4 + 0];
        l1 += hv * sWg[c * 4 + 1];
        l2 += hv * sWg[c * 4 + 2];
        l3 += hv * sWg[c * 4 + 3];
    }
#pragma unroll
    for (int o = 1; o < 8; o <<= 1) {
        l0 += __shfl_xor_sync(0xffffffffu, l0, o);
        l1 += __shfl_xor_sync(0xffffffffu, l1, o);
        l2 += __shfl_xor_sync(0xffffffffu, l2, o);
        l3 += __shfl_xor_sync(0xffffffffu, l3, o);
    }
    if (p == 0) {
        int gi = base + nn;
        if (gi < N_NODES) {
            l0 += sbg[0]; l1 += sbg[1]; l2 += sbg[2]; l3 += sbg[3];
            float m = fmaxf(fmaxf(l0, l1), fmaxf(l2, l3));
            float e0 = __expf(l0 - m), e1 = __expf(l1 - m), e2 = __expf(l2 - m), e3 = __expf(l3 - m);
            float inv = 1.f / (e0 + e1 + e2 + e3);
            float s0 = e0 * inv, s1 = e1 * inv, s2 = e2 * inv, s3 = e3 * inv;
            g_ss2[gi] = s0 * s0 + s1 * s1 + s2 * s2 + s3 * s3;
            float wpv = __ldg(&Wp[gi]);
            sws[nn][0] = s0 * wpv; sws[nn][1] = s1 * wpv;
            sws[nn][2] = s2 * wpv; sws[nn][3] = s3 * wpv;
            sswp[nn] = wpv;
        } else {
            sws[nn][0] = sws[nn][1] = sws[nn][2] = sws[nn][3] = 0.f;
            sswp[nn] = 0.f;
        }
    }
    __syncthreads();

    // P reduction: thread = (g, h), 32 staged nodes
    int g = tid >> 6, h = tid & 63;
    float acc = 0.f;
#pragma unroll
    for (int n2 = 0; n2 < 32; n2++)
        acc += sws[n2][g] * sh_h[n2][h];
    atomicAdd(&g_P[g * HID + h], acc);
    if (tid < 32) {
        float v = sswp[tid];
#pragma unroll
        for (int o = 16; o > 0; o >>= 1) v += __shfl_xor_sync(0xffffffffu, v, o);
        if (tid == 0) atomicAdd(&g_P[NGRP * HID], v);
    }
}

// ---------------- 4. per-user stats + fused epilogue ----------------
__global__ __launch_bounds__(64) void finalize_kernel(
    const int* __restrict__ cate, const float* __restrict__ gamma,
    const float* __restrict__ beta, const float* __restrict__ bp, float* __restrict__ out)
{
    int b = blockIdx.x;
    int h = threadIdx.x;
    float S1 = 0.f, S2 = 0.f;
#pragma unroll 1
    for (int l = 0; l < SEQL; l++) {
        int c = cate[b * SEQL + l];
        if (c != 0) {
            float gv = g_h[c * HID + h];
            S1 += gv;
            S2 += gv * gv * g_ss2[c];
        }
    }
    const float invn = 1.f / (float)(NGRP * SEQL);
    float mean = S1 * invn;
    float var  = S2 * invn - mean * mean;
    float inv  = rsqrtf(var + 1e-5f);
    float ga = gamma[h], be = beta[h];
    float Swp = g_P[NGRP * HID];
    float bpv = bp[0];
    float k1 = inv * ga;
    float addc = be * Swp + bpv;
    float ms = mean * Swp;
#pragma unroll
    for (int g = 0; g < NGRP; g++) {
        out[(b * NGRP + g) * HID + h] = k1 * (g_P[g * HID + h] - ms) + addc;
    }
}

// ---------------- launch ----------------
extern "C" void kernel_launch(void* const* d_in, const int* in_sizes, int n_in,
                              void* d_out, int out_size)
{
    const int*   cate  = (const int*)  d_in[0];
    const float* adj   = (const float*)d_in[1];
    const float* emb   = (const float*)d_in[2];
    const float* Wq    = (const float*)d_in[3];
    const float* Wk    = (const float*)d_in[4];
    const float* Wv    = (const float*)d_in[5];
    const float* Wg    = (const float*)d_in[6];
    const float* bg    = (const float*)d_in[7];
    const float* Wp    = (const float*)d_in[8];
    const float* bp    = (const float*)d_in[9];
    const float* gamma = (const float*)d_in[10];
    const float* beta  = (const float*)d_in[11];
    float* out = (float*)d_out;

    static bool attr_set = false;
    if (!attr_set) {
        cudaFuncSetAttribute(magna_kernel,
                             cudaFuncAttributeMaxDynamicSharedMemorySize, MAGNA_SMEM);
        attr_set = true;
    }

    build_csr<<<N_NODES, 128>>>(adj);

    for (int l = 0; l < 2; l++) {
        magna_kernel<<<MAGNA_GRID, MAGNA_THREADS, MAGNA_SMEM>>>(
            emb, (l == 0) ? 0 : 1,
            Wq + l * HID * HID, Wk + l * HID * HID, Wv + l * HID * HID,
            (l == 0) ? emb : nullptr, (l == 0) ? 1 : 2, l * 4);
    }

    cluster_kernel<<<(N_NODES + 31) / 32, 256>>>(Wg, bg, Wp);
    finalize_kernel<<<BATCH, HID>>>(cate, gamma, beta, bp, out);
}

// round 12
// speedup vs baseline: 1.1092x; 1.0217x over previous
#include <cuda_runtime.h>
#include <cuda_bf16.h>
#include <math.h>

#define N_NODES   3000
#define HID       64
#define MAXD      128
#define NGRP      4
#define BATCH     256
#define SEQL      50
#define MAGNA_GRID   148
#define ROWS_PER_BLK 21
#define MAGNA_THREADS (ROWS_PER_BLK * 32)
#define NSLOTS    16

// dynamic smem layout for mega: [sedge 21504][sW 49152][sh 5460]
#define SM_EDGE_BYTES (ROWS_PER_BLK * MAXD * 8)
#define SM_W_BYTES    (3 * HID * HID * 4)
#define SM_H_BYTES    (ROWS_PER_BLK * (HID + 1) * 4)
#define MAGNA_SMEM    (SM_EDGE_BYTES + SM_W_BYTES + SM_H_BYTES)

// ---------------- scratch (device globals; no allocation) ----------------
__device__ int   g_col[N_NODES * MAXD];
__device__ int   g_deg[N_NODES];
__device__ int   g_degp[N_NODES];
__device__ __align__(16) float g_q  [N_NODES * HID];
__device__ __align__(16) float g_k  [N_NODES * HID];
__device__ __align__(16) float g_v  [N_NODES * HID];
__device__ __align__(16) float g_z0 [N_NODES * HID];
__device__ __align__(16) float g_z1 [N_NODES * HID];
__device__ __align__(16) float g_z2 [N_NODES * HID];
__device__ __align__(16) float g_h  [N_NODES * HID];
__device__ float g_ss2[N_NODES];
__device__ float g_P  [NGRP * HID + 1];   // [0..255]=P[g,h], [256]=sum(Wp)
__device__ unsigned g_bar[NSLOTS];        // grid-barrier counters (zeroed each replay)

// ---------------- grid barrier (148 blocks, one per SM -> deadlock-free) ----------------
__device__ __forceinline__ void grid_barrier(int slot) {
    __syncthreads();
    if (threadIdx.x == 0) {
        __threadfence();
        atomicAdd(&g_bar[slot], 1u);
        unsigned v;
        do {
            asm volatile("ld.global.acquire.gpu.u32 %0, [%1];"
                         : "=r"(v) : "l"(&g_bar[slot]));
            if (v >= (unsigned)gridDim.x) break;
            __nanosleep(64);
        } while (true);
    }
    __syncthreads();
}

// ---------------- 1. build CSR from dense adj (+ zero accumulators/barriers) ----------------
__global__ void build_csr(const float* __restrict__ adj) {
    int i = blockIdx.x;
    if (i == 0) {
        for (int t = threadIdx.x; t <= NGRP * HID; t += blockDim.x) g_P[t] = 0.f;
        if (threadIdx.x < NSLOTS) g_bar[threadIdx.x] = 0u;
    }
    __shared__ int cnt;
    if (threadIdx.x == 0) cnt = 0;
    __syncthreads();
    const float4* row = reinterpret_cast<const float4*>(adj + (size_t)i * N_NODES);
    for (int j4 = threadIdx.x; j4 < N_NODES / 4; j4 += blockDim.x) {
        float4 f = row[j4];
        int j = j4 * 4;
        if (f.x > 0.f) { int p = atomicAdd(&cnt, 1); if (p < MAXD) g_col[i * MAXD + p] = j; }
        if (f.y > 0.f) { int p = atomicAdd(&cnt, 1); if (p < MAXD) g_col[i * MAXD + p] = j + 1; }
        if (f.z > 0.f) { int p = atomicAdd(&cnt, 1); if (p < MAXD) g_col[i * MAXD + p] = j + 2; }
        if (f.w > 0.f) { int p = atomicAdd(&cnt, 1); if (p < MAXD) g_col[i * MAXD + p] = j + 3; }
    }
    __syncthreads();
    int deg = min(cnt, MAXD);
    int degp = min((deg + 7) & ~7, MAXD);
    if (threadIdx.x == 0) { g_deg[i] = deg; g_degp[i] = degp; }
    for (int p = deg + (int)threadIdx.x; p < degp; p += blockDim.x) g_col[i * MAXD + p] = 0;
}

// ---------------- 2. mega persistent kernel: 2 MAGNA layers + cluster + finalize ----------------
// Barrier slots: layer0 {0:qkv, 1..3:hops}, 4:inter-layer, layer1 {5:qkv, 6..8:hops}, 9:pre-finalize.
__global__ __launch_bounds__(MAGNA_THREADS, 1) void mega_kernel(
    const float* __restrict__ emb,
    const float* __restrict__ Wq, const float* __restrict__ Wk, const float* __restrict__ Wv,
    const float* __restrict__ Wg, const float* __restrict__ bg,
    const float* __restrict__ Wp, const float* __restrict__ bp,
    const float* __restrict__ gamma, const float* __restrict__ beta,
    const int* __restrict__ cate, float* __restrict__ out)
{
    extern __shared__ char dyn[];
    float2 (*sedge)[MAXD] = reinterpret_cast<float2(*)[MAXD]>(dyn);
    float* sW = reinterpret_cast<float*>(dyn + SM_EDGE_BYTES);
    float* sh = reinterpret_cast<float*>(dyn + SM_EDGE_BYTES + SM_W_BYTES);
    __shared__ float sWg[HID * NGRP];
    __shared__ float sbg2[NGRP];
    __shared__ float sws[ROWS_PER_BLK][NGRP];
    __shared__ float sswp[ROWS_PER_BLK];

    int tid  = threadIdx.x;
    int w    = tid >> 5;
    int lane = tid & 31;
    int half = lane >> 4;
    int hl   = lane & 15;
    int h4   = hl * 4;
    int base = blockIdx.x * ROWS_PER_BLK;
    int i = base + w;
    bool active = (i < N_NODES);
    int deg = 0, degp = 0;
    if (active) { deg = g_deg[i]; degp = g_degp[i]; }

    for (int l = 0; l < 2; l++) {
        const float* Wql = Wq + l * HID * HID;
        const float* Wkl = Wk + l * HID * HID;
        const float* Wvl = Wv + l * HID * HID;
        int lb = (l == 0) ? 0 : 5;

        // ---- phase A: stage this layer's weights (+ emb tile on layer 0) ----
        {
            float4* sW4 = reinterpret_cast<float4*>(sW);
            const float4* wq4 = reinterpret_cast<const float4*>(Wql);
            const float4* wk4 = reinterpret_cast<const float4*>(Wkl);
            const float4* wv4 = reinterpret_cast<const float4*>(Wvl);
            for (int idx = tid; idx < HID * HID / 4; idx += MAGNA_THREADS) {
                sW4[idx]        = __ldg(&wq4[idx]);
                sW4[1024 + idx] = __ldg(&wk4[idx]);
                sW4[2048 + idx] = __ldg(&wv4[idx]);
            }
            if (l == 0) {
                for (int idx = tid; idx < ROWS_PER_BLK * HID; idx += MAGNA_THREADS) {
                    int r = idx >> 6, c = idx & 63;
                    int gi = base + r;
                    sh[r * (HID + 1) + c] = (gi < N_NODES) ? __ldg(&emb[gi * HID + c]) : 0.f;
                }
            }
        }
        __syncthreads();
        if (l == 1) grid_barrier(4);   // all blocks done with layer-0 hops before v/q/k overwrite

        // ---- phase B: QKV for own 21 rows (336 threads: mat x quad x 3-row group) ----
        if (tid < 336) {
            int m  = tid / 112;
            int rm = tid % 112;
            int quad = rm & 15;
            int rg   = rm >> 4;
            int r0   = rg * 3;
            const float4* wb = reinterpret_cast<const float4*>(sW) + m * 1024 + quad;
            float4 a0 = make_float4(0.f, 0.f, 0.f, 0.f);
            float4 a1 = a0, a2 = a0;
#pragma unroll
            for (int c = 0; c < HID; c++) {
                float4 ww = wb[c * 16];
                float h0 = sh[(r0 + 0) * (HID + 1) + c];
                float h1 = sh[(r0 + 1) * (HID + 1) + c];
                float h2 = sh[(r0 + 2) * (HID + 1) + c];
                a0.x += h0 * ww.x; a0.y += h0 * ww.y; a0.z += h0 * ww.z; a0.w += h0 * ww.w;
                a1.x += h1 * ww.x; a1.y += h1 * ww.y; a1.z += h1 * ww.z; a1.w += h1 * ww.w;
                a2.x += h2 * ww.x; a2.y += h2 * ww.y; a2.z += h2 * ww.z; a2.w += h2 * ww.w;
            }
            float* dst = (m == 0) ? g_q : (m == 1) ? g_k : g_v;
            float4 accs[3] = {a0, a1, a2};
#pragma unroll
            for (int i2 = 0; i2 < 3; i2++) {
                int gi = base + r0 + i2;
                if (gi < N_NODES)
                    *reinterpret_cast<float4*>(&dst[gi * HID + quad * 4]) = accs[i2];
            }
        }
        grid_barrier(lb);              // all q/k/v visible chip-wide

        // ---- phase C: edge dots + row softmax -> smem {j*HID, coef} ----
        if (active) {
            float4 qv = *reinterpret_cast<const float4*>(&g_q[i * HID + h4]);
            const int* __restrict__ cp = &g_col[i * MAXD];
            for (int s = 0; s < degp; s += 2) {
                int e = s + half;
                int j = __ldg(&cp[e]);
                float4 kv = __ldg(reinterpret_cast<const float4*>(&g_k[j * HID + h4]));
                float d = qv.x * kv.x + qv.y * kv.y + qv.z * kv.z + qv.w * kv.w;
                d += __shfl_xor_sync(0xffffffffu, d, 8);
                d += __shfl_xor_sync(0xffffffffu, d, 4);
                d += __shfl_xor_sync(0xffffffffu, d, 2);
                d += __shfl_xor_sync(0xffffffffu, d, 1);
                if (hl == 0) sedge[w][e] = make_float2(__int_as_float(j * HID), d);
            }
            __syncwarp();
            float vals[4];
#pragma unroll
            for (int t = 0; t < 4; t++) {
                int s = lane + 32 * t;
                vals[t] = (s < deg) ? sedge[w][s].y * 0.125f : -1e30f;
            }
            float m = fmaxf(fmaxf(vals[0], vals[1]), fmaxf(vals[2], vals[3]));
#pragma unroll
            for (int o = 16; o > 0; o >>= 1) m = fmaxf(m, __shfl_xor_sync(0xffffffffu, m, o));
            float sum = 0.f;
#pragma unroll
            for (int t = 0; t < 4; t++) {
                int s = lane + 32 * t;
                float e = (s < deg) ? __expf(vals[t] - m) : 0.f;
                vals[t] = e;
                sum += e;
            }
#pragma unroll
            for (int o = 16; o > 0; o >>= 1) sum += __shfl_xor_sync(0xffffffffu, sum, o);
            float inv = 1.f / sum;
#pragma unroll
            for (int t = 0; t < 4; t++) {
                int s = lane + 32 * t;
                if (s < degp) sedge[w][s].y = (s < deg) ? vals[t] * inv : 0.f;
            }
            __syncwarp();
        }

        // ---- phase D: 4 diffusion hops; hop3 adds resid from sh and refreshes sh ----
#pragma unroll
        for (int hop = 0; hop < 4; hop++) {
            if (hop > 0) grid_barrier(lb + hop);
            if (active) {
                const float* __restrict__ zin =
                    (hop == 0) ? g_v : (hop == 1) ? g_z0 : (hop == 2) ? g_z1 : g_z2;
                float* __restrict__ zout =
                    (hop == 0) ? g_z0 : (hop == 1) ? g_z1 : (hop == 2) ? g_z2 : g_h;
                const float4* __restrict__ s4 = reinterpret_cast<const float4*>(sedge[w]);
                float ax = 0.f, ay = 0.f, az = 0.f, aw = 0.f;
                for (int s = 0; s < degp; s += 8) {
                    int q = s >> 1;
#pragma unroll
                    for (int t = 0; t < 4; t++) {
                        float4 e2 = s4[q + t];
                        float cj = half ? e2.z : e2.x;
                        float cc = half ? e2.w : e2.y;
                        float4 z = __ldg(reinterpret_cast<const float4*>(&zin[__float_as_int(cj) + h4]));
                        ax += cc * z.x; ay += cc * z.y; az += cc * z.z; aw += cc * z.w;
                    }
                }
                ax += __shfl_down_sync(0xffffffffu, ax, 16);
                ay += __shfl_down_sync(0xffffffffu, ay, 16);
                az += __shfl_down_sync(0xffffffffu, az, 16);
                aw += __shfl_down_sync(0xffffffffu, aw, 16);
                if (half == 0) {
                    float4 v4 = __ldg(reinterpret_cast<const float4*>(&g_v[i * HID + h4]));
                    float4 r;
                    r.x = 0.85f * ax + 0.15f * v4.x;
                    r.y = 0.85f * ay + 0.15f * v4.y;
                    r.z = 0.85f * az + 0.15f * v4.z;
                    r.w = 0.85f * aw + 0.15f * v4.w;
                    if (hop == 3) {
                        int sb = w * (HID + 1) + h4;
                        r.x += sh[sb + 0]; r.y += sh[sb + 1];
                        r.z += sh[sb + 2]; r.w += sh[sb + 3];
                        sh[sb + 0] = r.x; sh[sb + 1] = r.y;
                        sh[sb + 2] = r.z; sh[sb + 3] = r.w;
                    }
                    *reinterpret_cast<float4*>(&zout[i * HID + h4]) = r;
                }
            }
        }
    }

    // ---- cluster phase: logits + softmax + ss2 + P partials (own rows, from smem) ----
    for (int idx = tid; idx < HID * NGRP; idx += MAGNA_THREADS) sWg[idx] = Wg[idx];
    if (tid < NGRP) sbg2[tid] = bg[tid];
    __syncthreads();
    if (lane < 16) {
        int sb = w * (HID + 1) + h4;
        float h0 = sh[sb + 0], h1 = sh[sb + 1], h2 = sh[sb + 2], h3 = sh[sb + 3];
        float lg0 = h0 * sWg[(h4+0)*4+0] + h1 * sWg[(h4+1)*4+0] + h2 * sWg[(h4+2)*4+0] + h3 * sWg[(h4+3)*4+0];
        float lg1 = h0 * sWg[(h4+0)*4+1] + h1 * sWg[(h4+1)*4+1] + h2 * sWg[(h4+2)*4+1] + h3 * sWg[(h4+3)*4+1];
        float lg2 = h0 * sWg[(h4+0)*4+2] + h1 * sWg[(h4+1)*4+2] + h2 * sWg[(h4+2)*4+2] + h3 * sWg[(h4+3)*4+2];
        float lg3 = h0 * sWg[(h4+0)*4+3] + h1 * sWg[(h4+1)*4+3] + h2 * sWg[(h4+2)*4+3] + h3 * sWg[(h4+3)*4+3];
#pragma unroll
        for (int o = 8; o > 0; o >>= 1) {
            lg0 += __shfl_xor_sync(0xffffu, lg0, o);
            lg1 += __shfl_xor_sync(0xffffu, lg1, o);
            lg2 += __shfl_xor_sync(0xffffu, lg2, o);
            lg3 += __shfl_xor_sync(0xffffu, lg3, o);
        }
        if (hl == 0) {
            if (active) {
                lg0 += sbg2[0]; lg1 += sbg2[1]; lg2 += sbg2[2]; lg3 += sbg2[3];
                float m = fmaxf(fmaxf(lg0, lg1), fmaxf(lg2, lg3));
                float e0 = __expf(lg0 - m), e1 = __expf(lg1 - m), e2 = __expf(lg2 - m), e3 = __expf(lg3 - m);
                float inv = 1.f / (e0 + e1 + e2 + e3);
                float s0 = e0 * inv, s1 = e1 * inv, s2 = e2 * inv, s3 = e3 * inv;
                g_ss2[i] = s0 * s0 + s1 * s1 + s2 * s2 + s3 * s3;
                float wpv = __ldg(&Wp[i]);
                sws[w][0] = s0 * wpv; sws[w][1] = s1 * wpv;
                sws[w][2] = s2 * wpv; sws[w][3] = s3 * wpv;
                sswp[w] = wpv;
            } else {
                sws[w][0] = sws[w][1] = sws[w][2] = sws[w][3] = 0.f;
                sswp[w] = 0.f;
            }
        }
    }
    __syncthreads();
    if (tid < 256) {
        int g = tid >> 6, h = tid & 63;
        float acc = 0.f;
#pragma unroll
        for (int r = 0; r < ROWS_PER_BLK; r++)
            acc += sws[r][g] * sh[r * (HID + 1) + h];
        atomicAdd(&g_P[g * HID + h], acc);
    }
    if (tid < 32) {
        float v = (tid < ROWS_PER_BLK) ? sswp[tid] : 0.f;
#pragma unroll
        for (int o = 16; o > 0; o >>= 1) v += __shfl_xor_sync(0xffffffffu, v, o);
        if (tid == 0) atomicAdd(&g_P[NGRP * HID], v);
    }
    grid_barrier(9);   // P, ss2, h all complete chip-wide

    // ---- finalize phase: 2 users per block ----
    if (tid < 128) {
        int which = tid >> 6;
        int u = blockIdx.x + which * MAGNA_GRID;
        if (u < BATCH) {
            int h = tid & 63;
            float S1 = 0.f, S2 = 0.f;
#pragma unroll 1
            for (int lq = 0; lq < SEQL; lq++) {
                int c = __ldg(&cate[u * SEQL + lq]);
                if (c != 0) {
                    float gv = __ldg(&g_h[c * HID + h]);
                    S1 += gv;
                    S2 += gv * gv * __ldg(&g_ss2[c]);
                }
            }
            const float invn = 1.f / (float)(NGRP * SEQL);
            float mean = S1 * invn;
            float var  = S2 * invn - mean * mean;
            float inv  = rsqrtf(var + 1e-5f);
            float ga = __ldg(&gamma[h]), be = __ldg(&beta[h]);
            float Swp = g_P[NGRP * HID];
            float bpv = __ldg(&bp[0]);
            float k1 = inv * ga;
            float addc = be * Swp + bpv;
            float ms = mean * Swp;
#pragma unroll
            for (int g = 0; g < NGRP; g++) {
                out[(u * NGRP + g) * HID + h] = k1 * (g_P[g * HID + h] - ms) + addc;
            }
        }
    }
}

// ---------------- launch ----------------
extern "C" void kernel_launch(void* const* d_in, const int* in_sizes, int n_in,
                              void* d_out, int out_size)
{
    const int*   cate  = (const int*)  d_in[0];
    const float* adj   = (const float*)d_in[1];
    const float* emb   = (const float*)d_in[2];
    const float* Wq    = (const float*)d_in[3];
    const float* Wk    = (const float*)d_in[4];
    const float* Wv    = (const float*)d_in[5];
    const float* Wg    = (const float*)d_in[6];
    const float* bg    = (const float*)d_in[7];
    const float* Wp    = (const float*)d_in[8];
    const float* bp    = (const float*)d_in[9];
    const float* gamma = (const float*)d_in[10];
    const float* beta  = (const float*)d_in[11];
    float* out = (float*)d_out;

    static bool attr_set = false;
    if (!attr_set) {
        cudaFuncSetAttribute(mega_kernel,
                             cudaFuncAttributeMaxDynamicSharedMemorySize, MAGNA_SMEM);
        attr_set = true;
    }

    build_csr<<<N_NODES, 128>>>(adj);
    mega_kernel<<<MAGNA_GRID, MAGNA_THREADS, MAGNA_SMEM>>>(
        emb, Wq, Wk, Wv, Wg, bg, Wp, bp, gamma, beta, cate, out);
}

// round 13
// speedup vs baseline: 1.1661x; 1.0513x over previous
#include <cuda_runtime.h>
#include <cuda_bf16.h>
#include <math.h>

#define N_NODES   3000
#define HID       64
#define MAXD      128
#define NGRP      4
#define BATCH     256
#define SEQL      50
#define RPB       11                 // rows per block
#define NWARPS    (RPB * 2)          // 2 warps per row
#define NTHREADS  (NWARPS * 32)      // 704
#define GRID2     296                // 2 blocks per SM x 148 SMs
#define NSLOTS    16

// dynamic smem layout: [sedge RPB*128*8][sW 49152][sh RPB*65*4]
#define SM_EDGE_BYTES (RPB * MAXD * 8)
#define SM_W_BYTES    (3 * HID * HID * 4)
#define SM_H_BYTES    (RPB * (HID + 1) * 4)
#define MAGNA_SMEM    (SM_EDGE_BYTES + SM_W_BYTES + SM_H_BYTES)

// ---------------- scratch (device globals; no allocation) ----------------
__device__ int   g_col[N_NODES * MAXD];
__device__ int   g_deg[N_NODES];
__device__ int   g_degp[N_NODES];
__device__ __align__(16) float g_q  [N_NODES * HID];
__device__ __align__(16) float g_k  [N_NODES * HID];
__device__ __align__(16) float g_v  [N_NODES * HID];
__device__ __align__(16) float g_z0 [N_NODES * HID];
__device__ __align__(16) float g_z1 [N_NODES * HID];
__device__ __align__(16) float g_z2 [N_NODES * HID];
__device__ __align__(16) float g_h  [N_NODES * HID];
__device__ float g_ss2[N_NODES];
__device__ float g_P  [NGRP * HID + 1];
__device__ unsigned g_bar[NSLOTS];

// ---------------- grid barrier (all blocks co-resident -> deadlock-free) ----------------
__device__ __forceinline__ void grid_barrier(int slot) {
    __syncthreads();
    if (threadIdx.x == 0) {
        __threadfence();
        atomicAdd(&g_bar[slot], 1u);
        unsigned v;
        do {
            asm volatile("ld.global.acquire.gpu.u32 %0, [%1];"
                         : "=r"(v) : "l"(&g_bar[slot]));
            if (v >= (unsigned)gridDim.x) break;
            __nanosleep(64);
        } while (true);
    }
    __syncthreads();
}

// ---------------- 1. build CSR from dense adj (+ zero accumulators/barriers) ----------------
__global__ void build_csr(const float* __restrict__ adj) {
    int i = blockIdx.x;
    if (i == 0) {
        for (int t = threadIdx.x; t <= NGRP * HID; t += blockDim.x) g_P[t] = 0.f;
        if (threadIdx.x < NSLOTS) g_bar[threadIdx.x] = 0u;
    }
    __shared__ int cnt;
    if (threadIdx.x == 0) cnt = 0;
    __syncthreads();
    const float4* row = reinterpret_cast<const float4*>(adj + (size_t)i * N_NODES);
    for (int j4 = threadIdx.x; j4 < N_NODES / 4; j4 += blockDim.x) {
        float4 f = row[j4];
        int j = j4 * 4;
        if (f.x > 0.f) { int p = atomicAdd(&cnt, 1); if (p < MAXD) g_col[i * MAXD + p] = j; }
        if (f.y > 0.f) { int p = atomicAdd(&cnt, 1); if (p < MAXD) g_col[i * MAXD + p] = j + 1; }
        if (f.z > 0.f) { int p = atomicAdd(&cnt, 1); if (p < MAXD) g_col[i * MAXD + p] = j + 2; }
        if (f.w > 0.f) { int p = atomicAdd(&cnt, 1); if (p < MAXD) g_col[i * MAXD + p] = j + 3; }
    }
    __syncthreads();
    int deg = min(cnt, MAXD);
    int degp = min((deg + 7) & ~7, MAXD);
    if (threadIdx.x == 0) { g_deg[i] = deg; g_degp[i] = degp; }
    for (int p = deg + (int)threadIdx.x; p < degp; p += blockDim.x) g_col[i * MAXD + p] = 0;
}

// ---------------- 2. mega persistent kernel ----------------
// Slots: layer0 {0:qkv, 1..3:hops}, 4:inter-layer, layer1 {5:qkv, 6..8:hops}, 9:pre-finalize.
__global__ __launch_bounds__(NTHREADS, 2) void mega_kernel(
    const float* __restrict__ emb,
    const float* __restrict__ Wq, const float* __restrict__ Wk, const float* __restrict__ Wv,
    const float* __restrict__ Wg, const float* __restrict__ bg,
    const float* __restrict__ Wp, const float* __restrict__ bp,
    const float* __restrict__ gamma, const float* __restrict__ beta,
    const int* __restrict__ cate, float* __restrict__ out)
{
    extern __shared__ char dyn[];
    float2 (*sedge)[MAXD] = reinterpret_cast<float2(*)[MAXD]>(dyn);
    float* sW = reinterpret_cast<float*>(dyn + SM_EDGE_BYTES);
    float* sh = reinterpret_cast<float*>(dyn + SM_EDGE_BYTES + SM_W_BYTES);
    __shared__ __align__(16) float4 spart[NWARPS][16];
    __shared__ float sWg[HID * NGRP];
    __shared__ float sbg2[NGRP];
    __shared__ float sws[RPB][NGRP];
    __shared__ float sswp[RPB];
    __shared__ float sf1[128], sf2[128];

    int tid  = threadIdx.x;
    int w    = tid >> 5;           // warp 0..21
    int lane = tid & 31;
    int r    = w >> 1;             // row slot 0..10
    int p    = w & 1;              // member of warp pair
    int half = lane >> 4;
    int hl   = lane & 15;
    int h4   = hl * 4;
    int base = blockIdx.x * RPB;
    int i = base + r;
    bool active = (i < N_NODES);
    int deg = 0, degp = 0;
    if (active) { deg = g_deg[i]; degp = g_degp[i]; }

    for (int l = 0; l < 2; l++) {
        const float* Wql = Wq + l * HID * HID;
        const float* Wkl = Wk + l * HID * HID;
        const float* Wvl = Wv + l * HID * HID;
        int lb = (l == 0) ? 0 : 5;

        // ---- phase A: stage weights (+ emb tile on layer 0) ----
        {
            float4* sW4 = reinterpret_cast<float4*>(sW);
            const float4* wq4 = reinterpret_cast<const float4*>(Wql);
            const float4* wk4 = reinterpret_cast<const float4*>(Wkl);
            const float4* wv4 = reinterpret_cast<const float4*>(Wvl);
            for (int idx = tid; idx < HID * HID / 4; idx += NTHREADS) {
                sW4[idx]        = __ldg(&wq4[idx]);
                sW4[1024 + idx] = __ldg(&wk4[idx]);
                sW4[2048 + idx] = __ldg(&wv4[idx]);
            }
            if (l == 0) {
                for (int idx = tid; idx < RPB * HID; idx += NTHREADS) {
                    int rr = idx >> 6, c = idx & 63;
                    int gi = base + rr;
                    sh[rr * (HID + 1) + c] = (gi < N_NODES) ? __ldg(&emb[gi * HID + c]) : 0.f;
                }
            }
        }
        __syncthreads();
        if (l == 1) grid_barrier(4);

        // ---- phase B: QKV (528 threads: mat x row x quad, one float4 acc each) ----
        if (tid < 3 * RPB * 16) {
            int m  = tid / (RPB * 16);
            int rm = tid - m * (RPB * 16);
            int r2 = rm >> 4;
            int quad = rm & 15;
            const float4* wb = reinterpret_cast<const float4*>(sW) + m * 1024 + quad;
            const float* hrow = &sh[r2 * (HID + 1)];
            float4 a = make_float4(0.f, 0.f, 0.f, 0.f);
#pragma unroll
            for (int c = 0; c < HID; c++) {
                float4 ww = wb[c * 16];
                float hv = hrow[c];
                a.x += hv * ww.x; a.y += hv * ww.y; a.z += hv * ww.z; a.w += hv * ww.w;
            }
            int gi = base + r2;
            if (gi < N_NODES) {
                float* dst = (m == 0) ? g_q : (m == 1) ? g_k : g_v;
                *reinterpret_cast<float4*>(&dst[gi * HID + quad * 4]) = a;
            }
        }
        grid_barrier(lb);

        // ---- phase C: edge dots (warp pair splits edges) + softmax (even warp) ----
        if (active) {
            float4 qv = *reinterpret_cast<const float4*>(&g_q[i * HID + h4]);
            const int* __restrict__ cp = &g_col[i * MAXD];
            for (int s = p * 2; s < degp; s += 4) {
                int e = s + half;
                int j = __ldg(&cp[e]);
                float4 kv = __ldg(reinterpret_cast<const float4*>(&g_k[j * HID + h4]));
                float d = qv.x * kv.x + qv.y * kv.y + qv.z * kv.z + qv.w * kv.w;
                d += __shfl_xor_sync(0xffffffffu, d, 8);
                d += __shfl_xor_sync(0xffffffffu, d, 4);
                d += __shfl_xor_sync(0xffffffffu, d, 2);
                d += __shfl_xor_sync(0xffffffffu, d, 1);
                if (hl == 0) sedge[r][e] = make_float2(__int_as_float(j * HID), d);
            }
        }
        __syncthreads();
        if (active && p == 0) {
            float vals[4];
#pragma unroll
            for (int t = 0; t < 4; t++) {
                int s = lane + 32 * t;
                vals[t] = (s < deg) ? sedge[r][s].y * 0.125f : -1e30f;
            }
            float m = fmaxf(fmaxf(vals[0], vals[1]), fmaxf(vals[2], vals[3]));
#pragma unroll
            for (int o = 16; o > 0; o >>= 1) m = fmaxf(m, __shfl_xor_sync(0xffffffffu, m, o));
            float sum = 0.f;
#pragma unroll
            for (int t = 0; t < 4; t++) {
                int s = lane + 32 * t;
                float e = (s < deg) ? __expf(vals[t] - m) : 0.f;
                vals[t] = e;
                sum += e;
            }
#pragma unroll
            for (int o = 16; o > 0; o >>= 1) sum += __shfl_xor_sync(0xffffffffu, sum, o);
            float inv = 1.f / sum;
#pragma unroll
            for (int t = 0; t < 4; t++) {
                int s = lane + 32 * t;
                if (s < degp) sedge[r][s].y = (s < deg) ? vals[t] * inv : 0.f;
            }
        }
        __syncthreads();

        // ---- phase D: 4 hops; warp pair interleaves 8-edge batches ----
#pragma unroll
        for (int hop = 0; hop < 4; hop++) {
            if (hop > 0) grid_barrier(lb + hop);
            const float* __restrict__ zin =
                (hop == 0) ? g_v : (hop == 1) ? g_z0 : (hop == 2) ? g_z1 : g_z2;
            float* __restrict__ zout =
                (hop == 0) ? g_z0 : (hop == 1) ? g_z1 : (hop == 2) ? g_z2 : g_h;
            float ax = 0.f, ay = 0.f, az = 0.f, aw = 0.f;
            if (active) {
                const float4* __restrict__ s4 = reinterpret_cast<const float4*>(sedge[r]);
                for (int s = p * 8; s < degp; s += 16) {
                    int q = s >> 1;
#pragma unroll
                    for (int t = 0; t < 4; t++) {
                        float4 e2 = s4[q + t];
                        float cj = half ? e2.z : e2.x;
                        float cc = half ? e2.w : e2.y;
                        float4 z = __ldg(reinterpret_cast<const float4*>(&zin[__float_as_int(cj) + h4]));
                        ax += cc * z.x; ay += cc * z.y; az += cc * z.z; aw += cc * z.w;
                    }
                }
                ax += __shfl_down_sync(0xffffffffu, ax, 16);
                ay += __shfl_down_sync(0xffffffffu, ay, 16);
                az += __shfl_down_sync(0xffffffffu, az, 16);
                aw += __shfl_down_sync(0xffffffffu, aw, 16);
            }
            if (half == 0) spart[w][hl] = make_float4(ax, ay, az, aw);
            __syncthreads();
            if (active && p == 0 && half == 0) {
                float4 pa = spart[w][hl];
                float4 pb = spart[w + 1][hl];
                float4 v4 = __ldg(reinterpret_cast<const float4*>(&g_v[i * HID + h4]));
                float4 rr;
                rr.x = 0.85f * (pa.x + pb.x) + 0.15f * v4.x;
                rr.y = 0.85f * (pa.y + pb.y) + 0.15f * v4.y;
                rr.z = 0.85f * (pa.z + pb.z) + 0.15f * v4.z;
                rr.w = 0.85f * (pa.w + pb.w) + 0.15f * v4.w;
                if (hop == 3) {
                    int sb = r * (HID + 1) + h4;
                    rr.x += sh[sb + 0]; rr.y += sh[sb + 1];
                    rr.z += sh[sb + 2]; rr.w += sh[sb + 3];
                    sh[sb + 0] = rr.x; sh[sb + 1] = rr.y;
                    sh[sb + 2] = rr.z; sh[sb + 3] = rr.w;
                }
                *reinterpret_cast<float4*>(&zout[i * HID + h4]) = rr;
            }
            __syncthreads();
        }
    }

    // ---- cluster phase: logits + softmax + ss2 + P partials (own rows, smem h) ----
    for (int idx = tid; idx < HID * NGRP; idx += NTHREADS) sWg[idx] = Wg[idx];
    if (tid < NGRP) sbg2[tid] = bg[tid];
    __syncthreads();
    if (w < RPB && lane < 16) {
        int i2 = base + w;
        int sb = w * (HID + 1) + h4;
        float h0 = sh[sb + 0], h1 = sh[sb + 1], h2 = sh[sb + 2], h3 = sh[sb + 3];
        float lg0 = h0 * sWg[(h4+0)*4+0] + h1 * sWg[(h4+1)*4+0] + h2 * sWg[(h4+2)*4+0] + h3 * sWg[(h4+3)*4+0];
        float lg1 = h0 * sWg[(h4+0)*4+1] + h1 * sWg[(h4+1)*4+1] + h2 * sWg[(h4+2)*4+1] + h3 * sWg[(h4+3)*4+1];
        float lg2 = h0 * sWg[(h4+0)*4+2] + h1 * sWg[(h4+1)*4+2] + h2 * sWg[(h4+2)*4+2] + h3 * sWg[(h4+3)*4+2];
        float lg3 = h0 * sWg[(h4+0)*4+3] + h1 * sWg[(h4+1)*4+3] + h2 * sWg[(h4+2)*4+3] + h3 * sWg[(h4+3)*4+3];
#pragma unroll
        for (int o = 8; o > 0; o >>= 1) {
            lg0 += __shfl_xor_sync(0xffffu, lg0, o);
            lg1 += __shfl_xor_sync(0xffffu, lg1, o);
            lg2 += __shfl_xor_sync(0xffffu, lg2, o);
            lg3 += __shfl_xor_sync(0xffffu, lg3, o);
        }
        if (hl == 0) {
            if (i2 < N_NODES) {
                lg0 += sbg2[0]; lg1 += sbg2[1]; lg2 += sbg2[2]; lg3 += sbg2[3];
                float m = fmaxf(fmaxf(lg0, lg1), fmaxf(lg2, lg3));
                float e0 = __expf(lg0 - m), e1 = __expf(lg1 - m), e2 = __expf(lg2 - m), e3 = __expf(lg3 - m);
                float inv = 1.f / (e0 + e1 + e2 + e3);
                float s0 = e0 * inv, s1 = e1 * inv, s2 = e2 * inv, s3 = e3 * inv;
                g_ss2[i2] = s0 * s0 + s1 * s1 + s2 * s2 + s3 * s3;
                float wpv = __ldg(&Wp[i2]);
                sws[w][0] = s0 * wpv; sws[w][1] = s1 * wpv;
                sws[w][2] = s2 * wpv; sws[w][3] = s3 * wpv;
                sswp[w] = wpv;
            } else {
                sws[w][0] = sws[w][1] = sws[w][2] = sws[w][3] = 0.f;
                sswp[w] = 0.f;
            }
        }
    }
    __syncthreads();
    if (tid < 256) {
        int g = tid >> 6, h = tid & 63;
        float acc = 0.f;
#pragma unroll
        for (int rr = 0; rr < RPB; rr++)
            acc += sws[rr][g] * sh[rr * (HID + 1) + h];
        atomicAdd(&g_P[g * HID + h], acc);
    }
    if (tid < 32) {
        float v = (tid < RPB) ? sswp[tid] : 0.f;
#pragma unroll
        for (int o = 16; o > 0; o >>= 1) v += __shfl_xor_sync(0xffffffffu, v, o);
        if (tid == 0) atomicAdd(&g_P[NGRP * HID], v);
    }
    grid_barrier(9);

    // ---- finalize phase: 1 user per block, 128 threads (sequence split 2-way) ----
    int u = blockIdx.x;
    if (u < BATCH && tid < 128) {
        int grp = tid >> 6;
        int h = tid & 63;
        float S1 = 0.f, S2 = 0.f;
        for (int lq = grp; lq < SEQL; lq += 2) {
            int c = __ldg(&cate[u * SEQL + lq]);
            if (c != 0) {
                float gv = __ldg(&g_h[c * HID + h]);
                S1 += gv;
                S2 += gv * gv * __ldg(&g_ss2[c]);
            }
        }
        sf1[tid] = S1;
        sf2[tid] = S2;
    }
    __syncthreads();
    if (u < BATCH && tid < 64) {
        int h = tid;
        float S1 = sf1[h] + sf1[h + 64];
        float S2 = sf2[h] + sf2[h + 64];
        const float invn = 1.f / (float)(NGRP * SEQL);
        float mean = S1 * invn;
        float var  = S2 * invn - mean * mean;
        float inv  = rsqrtf(var + 1e-5f);
        float ga = __ldg(&gamma[h]), be = __ldg(&beta[h]);
        float Swp = g_P[NGRP * HID];
        float bpv = __ldg(&bp[0]);
        float k1 = inv * ga;
        float addc = be * Swp + bpv;
        float ms = mean * Swp;
#pragma unroll
        for (int g = 0; g < NGRP; g++) {
            out[(u * NGRP + g) * HID + h] = k1 * (g_P[g * HID + h] - ms) + addc;
        }
    }
}

// ---------------- launch ----------------
extern "C" void kernel_launch(void* const* d_in, const int* in_sizes, int n_in,
                              void* d_out, int out_size)
{
    const int*   cate  = (const int*)  d_in[0];
    const float* adj   = (const float*)d_in[1];
    const float* emb   = (const float*)d_in[2];
    const float* Wq    = (const float*)d_in[3];
    const float* Wk    = (const float*)d_in[4];
    const float* Wv    = (const float*)d_in[5];
    const float* Wg    = (const float*)d_in[6];
    const float* bg    = (const float*)d_in[7];
    const float* Wp    = (const float*)d_in[8];
    const float* bp    = (const float*)d_in[9];
    const float* gamma = (const float*)d_in[10];
    const float* beta  = (const float*)d_in[11];
    float* out = (float*)d_out;

    static bool attr_set = false;
    if (!attr_set) {
        cudaFuncSetAttribute(mega_kernel,
                             cudaFuncAttributeMaxDynamicSharedMemorySize, MAGNA_SMEM);
        attr_set = true;
    }

    build_csr<<<N_NODES, 128>>>(adj);
    mega_kernel<<<GRID2, NTHREADS, MAGNA_SMEM>>>(
        emb, Wq, Wk, Wv, Wg, bg, Wp, bp, gamma, beta, cate, out);
}